// round 8
// baseline (speedup 1.0000x reference)
#include <cuda_runtime.h>
#include <math.h>

#define N 32
#define D 2097152
#define D4 (D/4)
#define TILE_C4 64          // 256 float columns per tile
#define NBLK 296
#define TPB 256
#define STR4 67             // smem row stride in float4 (bank-conflict-free pattern)
#define MAX_ITER 250
#define STOP_CRIT 1e-6f
#define EPS_LS 1e-8f

__device__ float g_partial[NBLK * N * N];
__device__ float g_G[N * N];

// ---------------------------------------------------------------------------
// Kernel 1: partial Gram. Each block computes the full 32x32 Gram over its
// slice of K (block-strided 256-column tiles), using 8x8 register tiles:
// 16 threads (ti,tj in 0..3) cover the 32x32 output with interleaved rows
// i = ti + 4r, j = tj + 4s; 16 groups per block each take a 16-column slice
// of the tile, then a log2 in-smem reduction combines the 16 groups.
// ---------------------------------------------------------------------------
__global__ __launch_bounds__(TPB)
void gram_partial_kernel(const float* __restrict__ vecs) {
    __shared__ float4 sm4[N * STR4];           // 34304 B tile buffer
    float* sbuf = (float*)sm4;                 // reused for reduction (<=32768 B)

    const int tid = threadIdx.x;
    const int blk = blockIdx.x;
    const int g  = tid >> 4;        // 0..15 : K-group
    const int t  = tid & 15;        // 0..15 : output-tile thread
    const int ti = t >> 2;          // 0..3
    const int tj = t & 3;           // 0..3

    float acc[64];
    #pragma unroll
    for (int e = 0; e < 64; ++e) acc[e] = 0.0f;

    const float4* __restrict__ v4 = (const float4*)vecs;
    const int numTiles = D / 256;   // 8192

    for (int tile = blk; tile < numTiles; tile += NBLK) {
        const int c4base = tile * TILE_C4;
        __syncthreads();
        // cooperative load: 32 rows x 64 float4
        #pragma unroll
        for (int l = 0; l < 8; ++l) {
            int idx = tid + l * TPB;
            int row = idx >> 6;
            int c4  = idx & 63;
            sm4[row * STR4 + c4] = v4[row * D4 + c4base + c4];
        }
        __syncthreads();

        #pragma unroll
        for (int kk = 0; kk < 4; ++kk) {
            const int k4 = (g << 2) + kk;
            float4 bv[8];
            #pragma unroll
            for (int s = 0; s < 8; ++s)
                bv[s] = sm4[(tj + 4 * s) * STR4 + k4];
            #pragma unroll
            for (int r = 0; r < 8; ++r) {
                float4 a = sm4[(ti + 4 * r) * STR4 + k4];
                #pragma unroll
                for (int s = 0; s < 8; ++s) {
                    acc[r * 8 + s] += a.x * bv[s].x + a.y * bv[s].y
                                    + a.z * bv[s].z + a.w * bv[s].w;
                }
            }
        }
    }

    // deterministic cross-group reduction: 16 -> 8 -> 4 -> 2 -> 1 groups
    for (int half = 8; half >= 1; half >>= 1) {
        __syncthreads();
        if (g >= half && g < 2 * half) {
            float* dst = sbuf + ((g - half) * 16 + t) * 64;
            #pragma unroll
            for (int e = 0; e < 64; ++e) dst[e] = acc[e];
        }
        __syncthreads();
        if (g < half) {
            const float* src = sbuf + (g * 16 + t) * 64;
            #pragma unroll
            for (int e = 0; e < 64; ++e) acc[e] += src[e];
        }
    }

    if (g == 0) {
        float* dst = g_partial + blk * (N * N);
        #pragma unroll
        for (int r = 0; r < 8; ++r)
            #pragma unroll
            for (int s = 0; s < 8; ++s)
                dst[(ti + 4 * r) * N + (tj + 4 * s)] = acc[r * 8 + s];
    }
}

// ---------------------------------------------------------------------------
// Kernel 2: deterministic reduction of per-block partials -> G
// ---------------------------------------------------------------------------
__global__ void gram_reduce_kernel() {
    int e = blockIdx.x * blockDim.x + threadIdx.x;   // 0..1023
    float s = 0.0f;
    for (int b = 0; b < NBLK; ++b) s += g_partial[b * (N * N) + e];
    g_G[e] = s;
}

// ---------------------------------------------------------------------------
// Kernel 3: min-norm Frank-Wolfe solver on 32x32 G; one warp, one lane per task.
// ---------------------------------------------------------------------------
__device__ __forceinline__ float warpsum(float v) {
    #pragma unroll
    for (int o = 16; o; o >>= 1) v += __shfl_xor_sync(0xffffffffu, v, o);
    return v;
}
__device__ __forceinline__ float warpmin(float v) {
    #pragma unroll
    for (int o = 16; o; o >>= 1) v = fminf(v, __shfl_xor_sync(0xffffffffu, v, o));
    return v;
}
__device__ __forceinline__ void line2(float v11, float v12, float v22,
                                      float* gamma, float* cost) {
    float gg = (v22 - v12) / (v11 + v22 - 2.0f * v12 + EPS_LS);
    float c  = v22 + gg * (v12 - v22);
    float gm = (v12 >= v22) ? 0.0f : gg;
    gm       = (v12 >= v11) ? 1.0f : gm;
    float cc = (v12 >= v22) ? v22 : c;
    cc       = (v12 >= v11) ? v11 : cc;
    *gamma = gm; *cost = cc;
}

__global__ void solver_kernel(float* __restrict__ out) {
    __shared__ float Gs[N][N + 1];
    __shared__ float solS[N], newpS[N];
    const unsigned FULL = 0xffffffffu;
    const int i = threadIdx.x;

    for (int j = 0; j < N; ++j) Gs[i][j] = g_G[i * N + j];
    __syncwarp();

    // ---- planar init: best pair by line-solver cost (first-min tiebreak) ----
    float bestCost = INFINITY, bestGamma = 0.0f;
    int bestLin = 1 << 30, bestI = 0, bestJ = 1;
    {
        float vii = Gs[i][i];
        int lin = i * 31 - (i * (i - 1)) / 2;    // triu row-major base index
        for (int j = i + 1; j < N; ++j, ++lin) {
            float gamma, cost;
            line2(vii, Gs[i][j], Gs[j][j], &gamma, &cost);
            if (cost < bestCost || (cost == bestCost && lin < bestLin)) {
                bestCost = cost; bestLin = lin; bestGamma = gamma;
                bestI = i; bestJ = j;
            }
        }
        #pragma unroll
        for (int o = 16; o; o >>= 1) {
            float oc = __shfl_down_sync(FULL, bestCost, o);
            int   ol = __shfl_down_sync(FULL, bestLin, o);
            float og = __shfl_down_sync(FULL, bestGamma, o);
            int   oi = __shfl_down_sync(FULL, bestI, o);
            int   oj = __shfl_down_sync(FULL, bestJ, o);
            if (oc < bestCost || (oc == bestCost && ol < bestLin)) {
                bestCost = oc; bestLin = ol; bestGamma = og; bestI = oi; bestJ = oj;
            }
        }
        bestGamma = __shfl_sync(FULL, bestGamma, 0);
        bestI = __shfl_sync(FULL, bestI, 0);
        bestJ = __shfl_sync(FULL, bestJ, 0);
    }
    float sol = (i == bestI) ? bestGamma : ((i == bestJ) ? (1.0f - bestGamma) : 0.0f);
    solS[i] = sol;
    __syncwarp();

    // ---- main iteration (break == reference's done-freeze) ----
    for (int it = 0; it < MAX_ITER; ++it) {
        // Gsol = G @ sol  (per-lane row dot)
        float Gsol = 0.0f;
        #pragma unroll
        for (int j = 0; j < N; ++j) Gsol += Gs[i][j] * solS[j];
        float grad = -Gsol;

        // _next_point
        float mean = warpsum(grad) * (1.0f / 32.0f);
        float proj = grad - mean;
        float tm1 = (proj < 0.0f) ? (-sol / proj) : INFINITY;
        float tm2 = (proj > 0.0f) ? ((1.0f - sol) / proj) : INFINITY;
        float m1 = warpmin((tm1 > 1e-7f) ? tm1 : INFINITY);
        float tt = (m1 < INFINITY) ? m1 : 1.0f;
        float m2 = warpmin((tm2 > 1e-7f) ? tm2 : INFINITY);
        tt = fminf(tt, m2);
        float nxt = proj * tt + sol;

        // _proj_simplex: descending bitonic sort across the warp
        float s = nxt;
        #pragma unroll
        for (int k = 2; k <= 32; k <<= 1) {
            #pragma unroll
            for (int j = k >> 1; j > 0; j >>= 1) {
                float o = __shfl_xor_sync(FULL, s, j);
                bool lower = (i & j) == 0;
                bool asc   = (i & k) != 0;
                s = (lower == asc) ? fminf(s, o) : fmaxf(s, o);
            }
        }
        // inclusive prefix sum of sorted values
        float cs = s;
        #pragma unroll
        for (int o = 1; o < 32; o <<= 1) {
            float v = __shfl_up_sync(FULL, cs, o);
            if (i >= o) cs += v;
        }
        float tmpmax = (cs - 1.0f) / (float)(i + 1);
        float snext = __shfl_down_sync(FULL, s, 1);
        bool cond = (i < 31) && (tmpmax > snext);
        unsigned bal = __ballot_sync(FULL, cond);
        int first = bal ? (__ffs(bal) - 1) : 31;
        float tmax = __shfl_sync(FULL, tmpmax, first);
        float newp = fmaxf(nxt - tmax, 0.0f);

        __syncwarp();
        newpS[i] = newp;
        __syncwarp();

        float Gn = 0.0f;
        #pragma unroll
        for (int j = 0; j < N; ++j) Gn += Gs[i][j] * newpS[j];

        float v11 = warpsum(sol * Gsol);
        float v12 = warpsum(sol * Gn);
        float v22 = warpsum(newp * Gn);
        float gamma, cost;
        line2(v11, v12, v22, &gamma, &cost);

        float ns = gamma * sol + (1.0f - gamma) * newp;
        float diff = warpsum(fabsf(ns - sol));
        if (diff < STOP_CRIT) break;   // reference freezes OLD sol from here on
        sol = ns;
        __syncwarp();
        solS[i] = sol;
        __syncwarp();
    }

    out[i] = sol;
}

// ---------------------------------------------------------------------------
extern "C" void kernel_launch(void* const* d_in, const int* in_sizes, int n_in,
                              void* d_out, int out_size) {
    const float* vecs = (const float*)d_in[0];
    float* out = (float*)d_out;
    (void)in_sizes; (void)n_in; (void)out_size;

    gram_partial_kernel<<<NBLK, TPB>>>(vecs);
    gram_reduce_kernel<<<8, 128>>>();
    solver_kernel<<<1, 32>>>(out);
}

// round 9
// speedup vs baseline: 1.9148x; 1.9148x over previous
#include <cuda_runtime.h>
#include <math.h>

#define N 32
#define D 2097152
#define D4 (D/4)
#define TILE_C4 64          // 256 float columns per tile
#define NBLK 296
#define TPB 256
#define STR4 67             // smem row stride in float4 (bank-conflict-free pattern)
#define BUF_F4 (N * STR4)   // float4s per buffer
#define SMEM_BYTES (2 * BUF_F4 * 16)
#define MAX_ITER 250
#define STOP_CRIT 1e-6f
#define EPS_LS 1e-8f

__device__ float g_partial[NBLK * N * N];
__device__ float g_G[N * N];

// ---------------------------------------------------------------------------
// Packed f32x2 helpers (Blackwell FFMA2 — only reachable via PTX)
// ---------------------------------------------------------------------------
__device__ __forceinline__ void ffma2(unsigned long long& d,
                                      unsigned long long a,
                                      unsigned long long b) {
    asm("fma.rn.f32x2 %0, %1, %2, %0;" : "+l"(d) : "l"(a), "l"(b));
}
__device__ __forceinline__ float2 ull2f2(unsigned long long v) {
    float2 r;
    asm("mov.b64 {%0, %1}, %2;" : "=f"(r.x), "=f"(r.y) : "l"(v));
    return r;
}
__device__ __forceinline__ void cp16(unsigned dst, const void* src) {
    asm volatile("cp.async.cg.shared.global [%0], [%1], 16;\n"
                 :: "r"(dst), "l"(src));
}

// ---------------------------------------------------------------------------
// Kernel 1: partial Gram. 8x8 register tiles (16 output-threads x 16 k-groups),
// f32x2 packed accumulation, 2-deep cp.async double-buffered tile pipeline.
// ---------------------------------------------------------------------------
__global__ __launch_bounds__(TPB, 1)
void gram_partial_kernel(const float* __restrict__ vecs) {
    extern __shared__ float4 smem_dyn[];

    const int tid = threadIdx.x;
    const int blk = blockIdx.x;
    const int g  = tid >> 4;        // 0..15 : K-group
    const int t  = tid & 15;        // 0..15 : output-tile thread
    const int ti = t >> 2;          // 0..3
    const int tj = t & 3;           // 0..3

    unsigned long long acc[64];
    #pragma unroll
    for (int e = 0; e < 64; ++e) acc[e] = 0ULL;

    const float4* __restrict__ v4 = (const float4*)vecs;
    const int numTiles = D / 256;   // 8192
    const int nT = (numTiles - blk + NBLK - 1) / NBLK;

    const unsigned sbase = (unsigned)__cvta_generic_to_shared(smem_dyn);
    const int c4 = tid & 63;        // column slot (constant per thread)
    const int r0 = tid >> 6;        // base row (rows r0, r0+4, ..., r0+28)

    // prefetch tile m into buffer b
    auto prefetch = [&](int m, int b) {
        const int tile = blk + m * NBLK;
        const float4* src0 = v4 + (size_t)tile * TILE_C4 + c4;
        const unsigned dst0 = sbase + (unsigned)b * (BUF_F4 * 16) + c4 * 16;
        #pragma unroll
        for (int l = 0; l < 8; ++l) {
            const int row = r0 + 4 * l;
            cp16(dst0 + row * (STR4 * 16), src0 + (size_t)row * D4);
        }
    };

    if (0 < nT) prefetch(0, 0);
    asm volatile("cp.async.commit_group;\n");
    if (1 < nT) prefetch(1, 1);
    asm volatile("cp.async.commit_group;\n");

    for (int m = 0; m < nT; ++m) {
        asm volatile("cp.async.wait_group 1;\n");   // group m complete
        __syncthreads();

        const ulonglong2* __restrict__ sm8 =
            (const ulonglong2*)(smem_dyn + (m & 1) * BUF_F4);

        #pragma unroll
        for (int kk = 0; kk < 4; ++kk) {
            const int k4 = (g << 2) + kk;
            ulonglong2 bv[8];
            #pragma unroll
            for (int s = 0; s < 8; ++s)
                bv[s] = sm8[(tj + 4 * s) * STR4 + k4];
            #pragma unroll
            for (int r = 0; r < 8; ++r) {
                ulonglong2 a = sm8[(ti + 4 * r) * STR4 + k4];
                #pragma unroll
                for (int s = 0; s < 8; ++s) {
                    ffma2(acc[r * 8 + s], a.x, bv[s].x);
                    ffma2(acc[r * 8 + s], a.y, bv[s].y);
                }
            }
        }

        __syncthreads();                // all warps done reading buf[m&1]
        if (m + 2 < nT) prefetch(m + 2, m & 1);
        asm volatile("cp.async.commit_group;\n");
    }

    asm volatile("cp.async.wait_group 0;\n");
    __syncthreads();

    // collapse packed pairs -> scalar accumulators
    float facc[64];
    #pragma unroll
    for (int e = 0; e < 64; ++e) {
        float2 p = ull2f2(acc[e]);
        facc[e] = p.x + p.y;
    }

    // deterministic cross-group reduction: 16 -> 8 -> 4 -> 2 -> 1 groups
    float* sbuf = (float*)smem_dyn;     // reuse tile buffers (<= 33 KB used)
    for (int half = 8; half >= 1; half >>= 1) {
        __syncthreads();
        if (g >= half && g < 2 * half) {
            float* dst = sbuf + ((g - half) * 16 + t) * 64;
            #pragma unroll
            for (int e = 0; e < 64; ++e) dst[e] = facc[e];
        }
        __syncthreads();
        if (g < half) {
            const float* src = sbuf + (g * 16 + t) * 64;
            #pragma unroll
            for (int e = 0; e < 64; ++e) facc[e] += src[e];
        }
    }

    if (g == 0) {
        float* dst = g_partial + blk * (N * N);
        #pragma unroll
        for (int r = 0; r < 8; ++r)
            #pragma unroll
            for (int s = 0; s < 8; ++s)
                dst[(ti + 4 * r) * N + (tj + 4 * s)] = facc[r * 8 + s];
    }
}

// ---------------------------------------------------------------------------
// Kernel 2: deterministic reduction of per-block partials -> G
// ---------------------------------------------------------------------------
__global__ void gram_reduce_kernel() {
    int e = blockIdx.x * blockDim.x + threadIdx.x;   // 0..1023
    float s = 0.0f;
    for (int b = 0; b < NBLK; ++b) s += g_partial[b * (N * N) + e];
    g_G[e] = s;
}

// ---------------------------------------------------------------------------
// Kernel 3: min-norm Frank-Wolfe solver on 32x32 G; one warp, one lane per task.
// ---------------------------------------------------------------------------
__device__ __forceinline__ float warpsum(float v) {
    #pragma unroll
    for (int o = 16; o; o >>= 1) v += __shfl_xor_sync(0xffffffffu, v, o);
    return v;
}
__device__ __forceinline__ float warpmin(float v) {
    #pragma unroll
    for (int o = 16; o; o >>= 1) v = fminf(v, __shfl_xor_sync(0xffffffffu, v, o));
    return v;
}
__device__ __forceinline__ void line2(float v11, float v12, float v22,
                                      float* gamma, float* cost) {
    float gg = (v22 - v12) / (v11 + v22 - 2.0f * v12 + EPS_LS);
    float c  = v22 + gg * (v12 - v22);
    float gm = (v12 >= v22) ? 0.0f : gg;
    gm       = (v12 >= v11) ? 1.0f : gm;
    float cc = (v12 >= v22) ? v22 : c;
    cc       = (v12 >= v11) ? v11 : cc;
    *gamma = gm; *cost = cc;
}

__global__ void solver_kernel(float* __restrict__ out) {
    __shared__ float Gs[N][N + 1];
    __shared__ float solS[N], newpS[N];
    const unsigned FULL = 0xffffffffu;
    const int i = threadIdx.x;

    for (int j = 0; j < N; ++j) Gs[i][j] = g_G[i * N + j];
    __syncwarp();

    // ---- planar init: best pair by line-solver cost (first-min tiebreak) ----
    float bestCost = INFINITY, bestGamma = 0.0f;
    int bestLin = 1 << 30, bestI = 0, bestJ = 1;
    {
        float vii = Gs[i][i];
        int lin = i * 31 - (i * (i - 1)) / 2;    // triu row-major base index
        for (int j = i + 1; j < N; ++j, ++lin) {
            float gamma, cost;
            line2(vii, Gs[i][j], Gs[j][j], &gamma, &cost);
            if (cost < bestCost || (cost == bestCost && lin < bestLin)) {
                bestCost = cost; bestLin = lin; bestGamma = gamma;
                bestI = i; bestJ = j;
            }
        }
        #pragma unroll
        for (int o = 16; o; o >>= 1) {
            float oc = __shfl_down_sync(FULL, bestCost, o);
            int   ol = __shfl_down_sync(FULL, bestLin, o);
            float og = __shfl_down_sync(FULL, bestGamma, o);
            int   oi = __shfl_down_sync(FULL, bestI, o);
            int   oj = __shfl_down_sync(FULL, bestJ, o);
            if (oc < bestCost || (oc == bestCost && ol < bestLin)) {
                bestCost = oc; bestLin = ol; bestGamma = og; bestI = oi; bestJ = oj;
            }
        }
        bestGamma = __shfl_sync(FULL, bestGamma, 0);
        bestI = __shfl_sync(FULL, bestI, 0);
        bestJ = __shfl_sync(FULL, bestJ, 0);
    }
    float sol = (i == bestI) ? bestGamma : ((i == bestJ) ? (1.0f - bestGamma) : 0.0f);
    solS[i] = sol;
    __syncwarp();

    // ---- main iteration (break == reference's done-freeze) ----
    for (int it = 0; it < MAX_ITER; ++it) {
        float Gsol = 0.0f;
        #pragma unroll
        for (int j = 0; j < N; ++j) Gsol += Gs[i][j] * solS[j];
        float grad = -Gsol;

        // _next_point
        float mean = warpsum(grad) * (1.0f / 32.0f);
        float proj = grad - mean;
        float tm1 = (proj < 0.0f) ? (-sol / proj) : INFINITY;
        float tm2 = (proj > 0.0f) ? ((1.0f - sol) / proj) : INFINITY;
        float m1 = warpmin((tm1 > 1e-7f) ? tm1 : INFINITY);
        float tt = (m1 < INFINITY) ? m1 : 1.0f;
        float m2 = warpmin((tm2 > 1e-7f) ? tm2 : INFINITY);
        tt = fminf(tt, m2);
        float nxt = proj * tt + sol;

        // _proj_simplex: descending bitonic sort across the warp
        float s = nxt;
        #pragma unroll
        for (int k = 2; k <= 32; k <<= 1) {
            #pragma unroll
            for (int j = k >> 1; j > 0; j >>= 1) {
                float o = __shfl_xor_sync(FULL, s, j);
                bool lower = (i & j) == 0;
                bool asc   = (i & k) != 0;
                s = (lower == asc) ? fminf(s, o) : fmaxf(s, o);
            }
        }
        float cs = s;
        #pragma unroll
        for (int o = 1; o < 32; o <<= 1) {
            float v = __shfl_up_sync(FULL, cs, o);
            if (i >= o) cs += v;
        }
        float tmpmax = (cs - 1.0f) / (float)(i + 1);
        float snext = __shfl_down_sync(FULL, s, 1);
        bool cond = (i < 31) && (tmpmax > snext);
        unsigned bal = __ballot_sync(FULL, cond);
        int first = bal ? (__ffs(bal) - 1) : 31;
        float tmax = __shfl_sync(FULL, tmpmax, first);
        float newp = fmaxf(nxt - tmax, 0.0f);

        __syncwarp();
        newpS[i] = newp;
        __syncwarp();

        float Gn = 0.0f;
        #pragma unroll
        for (int j = 0; j < N; ++j) Gn += Gs[i][j] * newpS[j];

        float v11 = warpsum(sol * Gsol);
        float v12 = warpsum(sol * Gn);
        float v22 = warpsum(newp * Gn);
        float gamma, cost;
        line2(v11, v12, v22, &gamma, &cost);

        float ns = gamma * sol + (1.0f - gamma) * newp;
        float diff = warpsum(fabsf(ns - sol));
        if (diff < STOP_CRIT) break;   // reference freezes OLD sol from here on
        sol = ns;
        __syncwarp();
        solS[i] = sol;
        __syncwarp();
    }

    out[i] = sol;
}

// ---------------------------------------------------------------------------
extern "C" void kernel_launch(void* const* d_in, const int* in_sizes, int n_in,
                              void* d_out, int out_size) {
    const float* vecs = (const float*)d_in[0];
    float* out = (float*)d_out;
    (void)in_sizes; (void)n_in; (void)out_size;

    cudaFuncSetAttribute(gram_partial_kernel,
                         cudaFuncAttributeMaxDynamicSharedMemorySize, SMEM_BYTES);
    gram_partial_kernel<<<NBLK, TPB, SMEM_BYTES>>>(vecs);
    gram_reduce_kernel<<<8, 128>>>();
    solver_kernel<<<1, 32>>>(out);
}

// round 10
// speedup vs baseline: 1.9621x; 1.0247x over previous
#include <cuda_runtime.h>
#include <math.h>

#define N 32
#define D 2097152
#define D4 (D/4)
#define TILE_C4 64            // 256 float columns per tile
#define NBLK 148              // one block per SM, single wave
#define TPB 256
#define STR4 67               // smem row stride in float4 (conflict-free LDS pattern)
#define BUF_F4 (N * STR4)     // float4s per buffer
#define BUF_BYTES (BUF_F4 * 16)       // 34304
#define SMEM_BYTES (2 * BUF_BYTES)    // 68608
#define ROW_BYTES 1024        // 64 float4 per row per tile
#define TILE_BYTES (N * ROW_BYTES)    // 32768
#define MAX_ITER 250
#define STOP_CRIT 1e-6f
#define EPS_LS 1e-8f

__device__ float g_partial[NBLK * N * N];

// ---------------------------------------------------------------------------
// PTX helpers
// ---------------------------------------------------------------------------
__device__ __forceinline__ void ffma2(unsigned long long& d,
                                      unsigned long long a,
                                      unsigned long long b) {
    asm("fma.rn.f32x2 %0, %1, %2, %0;" : "+l"(d) : "l"(a), "l"(b));
}
__device__ __forceinline__ float2 ull2f2(unsigned long long v) {
    float2 r;
    asm("mov.b64 {%0, %1}, %2;" : "=f"(r.x), "=f"(r.y) : "l"(v));
    return r;
}
__device__ __forceinline__ void mbar_init(unsigned mbar, unsigned count) {
    asm volatile("mbarrier.init.shared.b64 [%0], %1;" :: "r"(mbar), "r"(count) : "memory");
}
__device__ __forceinline__ void mbar_expect_tx(unsigned mbar, unsigned bytes) {
    asm volatile("mbarrier.arrive.expect_tx.shared.b64 _, [%0], %1;"
                 :: "r"(mbar), "r"(bytes) : "memory");
}
__device__ __forceinline__ void mbar_wait(unsigned mbar, unsigned parity) {
    asm volatile(
        "{\n\t"
        ".reg .pred P;\n\t"
        "W_%=:\n\t"
        "mbarrier.try_wait.parity.acquire.cta.shared::cta.b64 P, [%0], %1, 0x989680;\n\t"
        "@P bra D_%=;\n\t"
        "bra W_%=;\n\t"
        "D_%=:\n\t"
        "}" :: "r"(mbar), "r"(parity) : "memory");
}
__device__ __forceinline__ void bulk_cp(unsigned dst, const void* src,
                                        unsigned bytes, unsigned mbar) {
    asm volatile(
        "cp.async.bulk.shared::cluster.global.mbarrier::complete_tx::bytes "
        "[%0], [%1], %2, [%3];"
        :: "r"(dst), "l"(src), "r"(bytes), "r"(mbar) : "memory");
}

// ---------------------------------------------------------------------------
// Kernel 1: partial Gram. 8x8 register tiles (16 output-threads x 16 k-groups),
// f32x2 packed accumulation, double-buffered cp.async.bulk pipeline (warp 0
// issues 32x 1KB row copies per tile; completion via mbarrier expect_tx).
// ---------------------------------------------------------------------------
__global__ __launch_bounds__(TPB, 1)
void gram_partial_kernel(const float* __restrict__ vecs) {
    extern __shared__ float4 smem_dyn[];
    __shared__ unsigned long long barmem[2];

    const int tid = threadIdx.x;
    const int blk = blockIdx.x;
    const int g  = tid >> 4;        // 0..15 : K-group
    const int t  = tid & 15;        // 0..15 : output-tile thread
    const int ti = t >> 2;          // 0..3
    const int tj = t & 3;           // 0..3

    unsigned long long acc[64];
    #pragma unroll
    for (int e = 0; e < 64; ++e) acc[e] = 0ULL;

    const int numTiles = D / 256;   // 8192
    const int nT = (numTiles - blk + NBLK - 1) / NBLK;

    const unsigned sbase = (unsigned)__cvta_generic_to_shared(smem_dyn);
    const unsigned bar0  = (unsigned)__cvta_generic_to_shared(&barmem[0]);
    const unsigned bar1  = (unsigned)__cvta_generic_to_shared(&barmem[1]);

    if (tid == 0) {
        mbar_init(bar0, 1);
        mbar_init(bar1, 1);
    }
    __syncthreads();

    const int lane = tid;           // only warp 0 (tid<32) uses this as row id

    // warp-0 collective: issue tile m into buffer b
    auto issue = [&](int m, int b) {
        const unsigned mbar = b ? bar1 : bar0;
        if (lane == 0) mbar_expect_tx(mbar, TILE_BYTES);
        __syncwarp();
        const int tile = blk + m * NBLK;
        const float* src = vecs + (size_t)lane * D + (size_t)tile * 256;
        const unsigned dst = sbase + (unsigned)b * BUF_BYTES
                                   + (unsigned)lane * (STR4 * 16);
        bulk_cp(dst, src, ROW_BYTES, mbar);
    };

    if (tid < 32) {
        if (0 < nT) issue(0, 0);
        if (1 < nT) issue(1, 1);
    }

    for (int m = 0; m < nT; ++m) {
        const int b = m & 1;
        mbar_wait(b ? bar1 : bar0, (m >> 1) & 1);

        const ulonglong2* __restrict__ sm8 =
            (const ulonglong2*)(smem_dyn + b * BUF_F4);

        #pragma unroll
        for (int kk = 0; kk < 4; ++kk) {
            const int k4 = (g << 2) + kk;
            ulonglong2 bv[8];
            #pragma unroll
            for (int s = 0; s < 8; ++s)
                bv[s] = sm8[(tj + 4 * s) * STR4 + k4];
            #pragma unroll
            for (int r = 0; r < 8; ++r) {
                ulonglong2 a = sm8[(ti + 4 * r) * STR4 + k4];
                #pragma unroll
                for (int s = 0; s < 8; ++s) {
                    ffma2(acc[r * 8 + s], a.x, bv[s].x);
                    ffma2(acc[r * 8 + s], a.y, bv[s].y);
                }
            }
        }

        __syncthreads();                 // all warps done reading buf b
        if (m + 2 < nT && tid < 32) issue(m + 2, b);
    }

    // collapse packed pairs -> scalar accumulators
    float facc[64];
    #pragma unroll
    for (int e = 0; e < 64; ++e) {
        float2 p = ull2f2(acc[e]);
        facc[e] = p.x + p.y;
    }

    __syncthreads();
    // deterministic cross-group reduction: 16 -> 8 -> 4 -> 2 -> 1 groups
    float* sbuf = (float*)smem_dyn;      // all async copies consumed by now
    for (int half = 8; half >= 1; half >>= 1) {
        __syncthreads();
        if (g >= half && g < 2 * half) {
            float* dst = sbuf + ((g - half) * 16 + t) * 64;
            #pragma unroll
            for (int e = 0; e < 64; ++e) dst[e] = facc[e];
        }
        __syncthreads();
        if (g < half) {
            const float* src = sbuf + (g * 16 + t) * 64;
            #pragma unroll
            for (int e = 0; e < 64; ++e) facc[e] += src[e];
        }
    }

    if (g == 0) {
        float* dst = g_partial + blk * (N * N);
        #pragma unroll
        for (int r = 0; r < 8; ++r)
            #pragma unroll
            for (int s = 0; s < 8; ++s)
                dst[(ti + 4 * r) * N + (tj + 4 * s)] = facc[r * 8 + s];
    }
}

// ---------------------------------------------------------------------------
// Kernel 2: fused partial-reduction + min-norm Frank-Wolfe solver.
// 1024 threads reduce the 148 partial Grams into smem; warp 0 then iterates.
// ---------------------------------------------------------------------------
__device__ __forceinline__ float warpsum(float v) {
    #pragma unroll
    for (int o = 16; o; o >>= 1) v += __shfl_xor_sync(0xffffffffu, v, o);
    return v;
}
__device__ __forceinline__ float warpmin(float v) {
    #pragma unroll
    for (int o = 16; o; o >>= 1) v = fminf(v, __shfl_xor_sync(0xffffffffu, v, o));
    return v;
}
__device__ __forceinline__ void line2(float v11, float v12, float v22,
                                      float* gamma, float* cost) {
    float gg = (v22 - v12) / (v11 + v22 - 2.0f * v12 + EPS_LS);
    float c  = v22 + gg * (v12 - v22);
    float gm = (v12 >= v22) ? 0.0f : gg;
    gm       = (v12 >= v11) ? 1.0f : gm;
    float cc = (v12 >= v22) ? v22 : c;
    cc       = (v12 >= v11) ? v11 : cc;
    *gamma = gm; *cost = cc;
}

__global__ void solver_kernel(float* __restrict__ out) {
    __shared__ float Gs[N][N + 1];
    __shared__ float solS[N], newpS[N];
    const unsigned FULL = 0xffffffffu;
    const int tid = threadIdx.x;

    // reduce 148 partials -> Gs (coalesced: thread e reads g_partial[b*1024+e])
    {
        float s = 0.0f;
        #pragma unroll 4
        for (int b = 0; b < NBLK; ++b) s += g_partial[b * (N * N) + tid];
        Gs[tid >> 5][tid & 31] = s;
    }
    __syncthreads();
    if (tid >= 32) return;

    const int i = tid;

    // ---- planar init: best pair by line-solver cost (first-min tiebreak) ----
    float bestCost = INFINITY, bestGamma = 0.0f;
    int bestLin = 1 << 30, bestI = 0, bestJ = 1;
    {
        float vii = Gs[i][i];
        int lin = i * 31 - (i * (i - 1)) / 2;    // triu row-major base index
        for (int j = i + 1; j < N; ++j, ++lin) {
            float gamma, cost;
            line2(vii, Gs[i][j], Gs[j][j], &gamma, &cost);
            if (cost < bestCost || (cost == bestCost && lin < bestLin)) {
                bestCost = cost; bestLin = lin; bestGamma = gamma;
                bestI = i; bestJ = j;
            }
        }
        #pragma unroll
        for (int o = 16; o; o >>= 1) {
            float oc = __shfl_down_sync(FULL, bestCost, o);
            int   ol = __shfl_down_sync(FULL, bestLin, o);
            float og = __shfl_down_sync(FULL, bestGamma, o);
            int   oi = __shfl_down_sync(FULL, bestI, o);
            int   oj = __shfl_down_sync(FULL, bestJ, o);
            if (oc < bestCost || (oc == bestCost && ol < bestLin)) {
                bestCost = oc; bestLin = ol; bestGamma = og; bestI = oi; bestJ = oj;
            }
        }
        bestGamma = __shfl_sync(FULL, bestGamma, 0);
        bestI = __shfl_sync(FULL, bestI, 0);
        bestJ = __shfl_sync(FULL, bestJ, 0);
    }
    float sol = (i == bestI) ? bestGamma : ((i == bestJ) ? (1.0f - bestGamma) : 0.0f);
    solS[i] = sol;
    __syncwarp();

    // ---- main iteration (break == reference's done-freeze) ----
    for (int it = 0; it < MAX_ITER; ++it) {
        float Gsol = 0.0f;
        #pragma unroll
        for (int j = 0; j < N; ++j) Gsol += Gs[i][j] * solS[j];
        float grad = -Gsol;

        // _next_point
        float mean = warpsum(grad) * (1.0f / 32.0f);
        float proj = grad - mean;
        float tm1 = (proj < 0.0f) ? (-sol / proj) : INFINITY;
        float tm2 = (proj > 0.0f) ? ((1.0f - sol) / proj) : INFINITY;
        float m1 = warpmin((tm1 > 1e-7f) ? tm1 : INFINITY);
        float tt = (m1 < INFINITY) ? m1 : 1.0f;
        float m2 = warpmin((tm2 > 1e-7f) ? tm2 : INFINITY);
        tt = fminf(tt, m2);
        float nxt = proj * tt + sol;

        // _proj_simplex: descending bitonic sort across the warp
        float s = nxt;
        #pragma unroll
        for (int k = 2; k <= 32; k <<= 1) {
            #pragma unroll
            for (int j = k >> 1; j > 0; j >>= 1) {
                float o = __shfl_xor_sync(FULL, s, j);
                bool lower = (i & j) == 0;
                bool asc   = (i & k) != 0;
                s = (lower == asc) ? fminf(s, o) : fmaxf(s, o);
            }
        }
        float cs = s;
        #pragma unroll
        for (int o = 1; o < 32; o <<= 1) {
            float v = __shfl_up_sync(FULL, cs, o);
            if (i >= o) cs += v;
        }
        float tmpmax = (cs - 1.0f) / (float)(i + 1);
        float snext = __shfl_down_sync(FULL, s, 1);
        bool cond = (i < 31) && (tmpmax > snext);
        unsigned bal = __ballot_sync(FULL, cond);
        int first = bal ? (__ffs(bal) - 1) : 31;
        float tmax = __shfl_sync(FULL, tmpmax, first);
        float newp = fmaxf(nxt - tmax, 0.0f);

        __syncwarp();
        newpS[i] = newp;
        __syncwarp();

        float Gn = 0.0f;
        #pragma unroll
        for (int j = 0; j < N; ++j) Gn += Gs[i][j] * newpS[j];

        float v11 = warpsum(sol * Gsol);
        float v12 = warpsum(sol * Gn);
        float v22 = warpsum(newp * Gn);
        float gamma, cost;
        line2(v11, v12, v22, &gamma, &cost);

        float ns = gamma * sol + (1.0f - gamma) * newp;
        float diff = warpsum(fabsf(ns - sol));
        if (diff < STOP_CRIT) break;   // reference freezes OLD sol from here on
        sol = ns;
        __syncwarp();
        solS[i] = sol;
        __syncwarp();
    }

    out[i] = sol;
}

// ---------------------------------------------------------------------------
extern "C" void kernel_launch(void* const* d_in, const int* in_sizes, int n_in,
                              void* d_out, int out_size) {
    const float* vecs = (const float*)d_in[0];
    float* out = (float*)d_out;
    (void)in_sizes; (void)n_in; (void)out_size;

    cudaFuncSetAttribute(gram_partial_kernel,
                         cudaFuncAttributeMaxDynamicSharedMemorySize, SMEM_BYTES);
    gram_partial_kernel<<<NBLK, TPB, SMEM_BYTES>>>(vecs);
    solver_kernel<<<1, 1024>>>(out);
}

// round 11
// speedup vs baseline: 1.9931x; 1.0158x over previous
#include <cuda_runtime.h>
#include <math.h>

#define N 32
#define D 2097152
#define D4 (D/4)
#define NBLK 148              // one block per SM, single wave
#define TPB 512
#define STR4 67               // smem row stride in float4 (conflict-free LDS pattern)
#define BUF_F4 (N * STR4)     // float4s per buffer (2144)
#define BUF_BYTES (BUF_F4 * 16)       // 34304
#define NBUF 3
#define SMEM_BYTES (NBUF * BUF_BYTES) // 102912
#define ROW_BYTES 1024        // 64 float4 per row per tile
#define TILE_BYTES (N * ROW_BYTES)    // 32768
#define MAX_ITER 250
#define STOP_CRIT 1e-6f
#define EPS_LS 1e-8f

__device__ float g_partial[NBLK * N * N];

// ---------------------------------------------------------------------------
// PTX helpers
// ---------------------------------------------------------------------------
__device__ __forceinline__ void ffma2(unsigned long long& d,
                                      unsigned long long a,
                                      unsigned long long b) {
    asm("fma.rn.f32x2 %0, %1, %2, %0;" : "+l"(d) : "l"(a), "l"(b));
}
__device__ __forceinline__ float2 ull2f2(unsigned long long v) {
    float2 r;
    asm("mov.b64 {%0, %1}, %2;" : "=f"(r.x), "=f"(r.y) : "l"(v));
    return r;
}
__device__ __forceinline__ void mbar_init(unsigned mbar, unsigned count) {
    asm volatile("mbarrier.init.shared.b64 [%0], %1;" :: "r"(mbar), "r"(count) : "memory");
}
__device__ __forceinline__ void mbar_expect_tx(unsigned mbar, unsigned bytes) {
    asm volatile("mbarrier.arrive.expect_tx.shared.b64 _, [%0], %1;"
                 :: "r"(mbar), "r"(bytes) : "memory");
}
__device__ __forceinline__ void mbar_wait(unsigned mbar, unsigned parity) {
    asm volatile(
        "{\n\t"
        ".reg .pred P;\n\t"
        "W_%=:\n\t"
        "mbarrier.try_wait.parity.acquire.cta.shared::cta.b64 P, [%0], %1, 0x989680;\n\t"
        "@P bra D_%=;\n\t"
        "bra W_%=;\n\t"
        "D_%=:\n\t"
        "}" :: "r"(mbar), "r"(parity) : "memory");
}
__device__ __forceinline__ void bulk_cp(unsigned dst, const void* src,
                                        unsigned bytes, unsigned mbar) {
    asm volatile(
        "cp.async.bulk.shared::cluster.global.mbarrier::complete_tx::bytes "
        "[%0], [%1], %2, [%3];"
        :: "r"(dst), "l"(src), "r"(bytes), "r"(mbar) : "memory");
}

// ---------------------------------------------------------------------------
// Kernel 1: partial Gram. 512 threads = 16 k-groups (one warp each) x 32
// output-threads; each output thread owns a 4x8 register tile of the 32x32
// output (rows ti+8r, cols tj+4s), f32x2 packed accumulation, triple-buffered
// cp.async.bulk pipeline (warp 0 issues 32x 1KB row copies per tile).
// ---------------------------------------------------------------------------
__global__ __launch_bounds__(TPB, 1)
void gram_partial_kernel(const float* __restrict__ vecs) {
    extern __shared__ float4 smem_dyn[];
    __shared__ unsigned long long barmem[NBUF];

    const int tid = threadIdx.x;
    const int blk = blockIdx.x;
    const int g  = tid >> 5;        // 0..15 : K-group (= warp id)
    const int t  = tid & 31;        // 0..31 : output-tile thread
    const int ti = t >> 2;          // 0..7
    const int tj = t & 3;           // 0..3

    unsigned long long acc[32];     // acc[r*8+s], r in 0..3, s in 0..7
    #pragma unroll
    for (int e = 0; e < 32; ++e) acc[e] = 0ULL;

    const int numTiles = D / 256;   // 8192
    const int nT = (numTiles - blk + NBLK - 1) / NBLK;

    const unsigned sbase = (unsigned)__cvta_generic_to_shared(smem_dyn);
    unsigned bar[NBUF];
    #pragma unroll
    for (int b = 0; b < NBUF; ++b)
        bar[b] = (unsigned)__cvta_generic_to_shared(&barmem[b]);

    if (tid == 0) {
        #pragma unroll
        for (int b = 0; b < NBUF; ++b) mbar_init(bar[b], 1);
    }
    __syncthreads();

    const int lane = tid;           // warp 0 only: row id 0..31

    // warp-0 collective: issue tile m into buffer m%NBUF
    auto issue = [&](int m) {
        const int b = m % NBUF;
        const unsigned mbar = bar[b];
        if (lane == 0) mbar_expect_tx(mbar, TILE_BYTES);
        __syncwarp();
        const int tile = blk + m * NBLK;
        const float* src = vecs + (size_t)lane * D + (size_t)tile * 256;
        const unsigned dst = sbase + (unsigned)b * BUF_BYTES
                                   + (unsigned)lane * (STR4 * 16);
        bulk_cp(dst, src, ROW_BYTES, mbar);
    };

    if (tid < 32) {
        if (0 < nT) issue(0);
        if (1 < nT) issue(1);
        if (2 < nT) issue(2);
    }

    for (int m = 0; m < nT; ++m) {
        const int b = m % NBUF;
        mbar_wait(bar[b], (m / NBUF) & 1);

        const ulonglong2* __restrict__ sm8 =
            (const ulonglong2*)(smem_dyn + b * BUF_F4);

        #pragma unroll
        for (int kk = 0; kk < 4; ++kk) {
            const int k4 = (g << 2) + kk;
            ulonglong2 av[4];
            #pragma unroll
            for (int r = 0; r < 4; ++r)
                av[r] = sm8[(ti + 8 * r) * STR4 + k4];
            #pragma unroll
            for (int half = 0; half < 2; ++half) {
                ulonglong2 bv[4];
                #pragma unroll
                for (int s4 = 0; s4 < 4; ++s4)
                    bv[s4] = sm8[(tj + 4 * (half * 4 + s4)) * STR4 + k4];
                #pragma unroll
                for (int r = 0; r < 4; ++r) {
                    #pragma unroll
                    for (int s4 = 0; s4 < 4; ++s4) {
                        const int e = r * 8 + half * 4 + s4;
                        ffma2(acc[e], av[r].x, bv[s4].x);
                        ffma2(acc[e], av[r].y, bv[s4].y);
                    }
                }
            }
        }

        __syncthreads();                 // all warps done reading buf b
        if (m + NBUF < nT && tid < 32) issue(m + NBUF);
    }

    // collapse packed pairs -> scalar accumulators
    float facc[32];
    #pragma unroll
    for (int e = 0; e < 32; ++e) {
        float2 p = ull2f2(acc[e]);
        facc[e] = p.x + p.y;
    }

    __syncthreads();
    // deterministic cross-group reduction: 16 -> 8 -> 4 -> 2 -> 1 groups
    float* sbuf = (float*)smem_dyn;      // all async copies consumed by now
    for (int half = 8; half >= 1; half >>= 1) {
        __syncthreads();
        if (g >= half && g < 2 * half) {
            float* dst = sbuf + ((g - half) * 32 + t) * 32;
            #pragma unroll
            for (int e = 0; e < 32; ++e) dst[e] = facc[e];
        }
        __syncthreads();
        if (g < half) {
            const float* src = sbuf + (g * 32 + t) * 32;
            #pragma unroll
            for (int e = 0; e < 32; ++e) facc[e] += src[e];
        }
    }

    if (g == 0) {
        float* dst = g_partial + blk * (N * N);
        #pragma unroll
        for (int r = 0; r < 4; ++r)
            #pragma unroll
            for (int s = 0; s < 8; ++s)
                dst[(ti + 8 * r) * N + (tj + 4 * s)] = facc[r * 8 + s];
    }
}

// ---------------------------------------------------------------------------
// Kernel 2: fused partial-reduction + min-norm Frank-Wolfe solver.
// 1024 threads reduce the 148 partial Grams into smem; warp 0 then iterates.
// ---------------------------------------------------------------------------
__device__ __forceinline__ float warpsum(float v) {
    #pragma unroll
    for (int o = 16; o; o >>= 1) v += __shfl_xor_sync(0xffffffffu, v, o);
    return v;
}
__device__ __forceinline__ float warpmin(float v) {
    #pragma unroll
    for (int o = 16; o; o >>= 1) v = fminf(v, __shfl_xor_sync(0xffffffffu, v, o));
    return v;
}
__device__ __forceinline__ void line2(float v11, float v12, float v22,
                                      float* gamma, float* cost) {
    float gg = (v22 - v12) / (v11 + v22 - 2.0f * v12 + EPS_LS);
    float c  = v22 + gg * (v12 - v22);
    float gm = (v12 >= v22) ? 0.0f : gg;
    gm       = (v12 >= v11) ? 1.0f : gm;
    float cc = (v12 >= v22) ? v22 : c;
    cc       = (v12 >= v11) ? v11 : cc;
    *gamma = gm; *cost = cc;
}

// 4-way split matvec: depth-8 chains + 2 adds instead of 32 serial FMAs
__device__ __forceinline__ float rowdot(const float* __restrict__ Grow,
                                        const float* __restrict__ x) {
    float p0 = 0.f, p1 = 0.f, p2 = 0.f, p3 = 0.f;
    #pragma unroll
    for (int j = 0; j < 8; ++j) {
        p0 += Grow[j]      * x[j];
        p1 += Grow[j + 8]  * x[j + 8];
        p2 += Grow[j + 16] * x[j + 16];
        p3 += Grow[j + 24] * x[j + 24];
    }
    return (p0 + p1) + (p2 + p3);
}

__global__ void solver_kernel(float* __restrict__ out) {
    __shared__ float Gs[N][N + 1];
    __shared__ float solS[N], newpS[N];
    const unsigned FULL = 0xffffffffu;
    const int tid = threadIdx.x;

    // reduce 148 partials -> Gs (coalesced: thread e reads g_partial[b*1024+e])
    {
        float s = 0.0f;
        #pragma unroll 4
        for (int b = 0; b < NBLK; ++b) s += g_partial[b * (N * N) + tid];
        Gs[tid >> 5][tid & 31] = s;
    }
    __syncthreads();
    if (tid >= 32) return;

    const int i = tid;

    // ---- planar init: best pair by line-solver cost (first-min tiebreak) ----
    float bestCost = INFINITY, bestGamma = 0.0f;
    int bestLin = 1 << 30, bestI = 0, bestJ = 1;
    {
        float vii = Gs[i][i];
        int lin = i * 31 - (i * (i - 1)) / 2;    // triu row-major base index
        for (int j = i + 1; j < N; ++j, ++lin) {
            float gamma, cost;
            line2(vii, Gs[i][j], Gs[j][j], &gamma, &cost);
            if (cost < bestCost || (cost == bestCost && lin < bestLin)) {
                bestCost = cost; bestLin = lin; bestGamma = gamma;
                bestI = i; bestJ = j;
            }
        }
        #pragma unroll
        for (int o = 16; o; o >>= 1) {
            float oc = __shfl_down_sync(FULL, bestCost, o);
            int   ol = __shfl_down_sync(FULL, bestLin, o);
            float og = __shfl_down_sync(FULL, bestGamma, o);
            int   oi = __shfl_down_sync(FULL, bestI, o);
            int   oj = __shfl_down_sync(FULL, bestJ, o);
            if (oc < bestCost || (oc == bestCost && ol < bestLin)) {
                bestCost = oc; bestLin = ol; bestGamma = og; bestI = oi; bestJ = oj;
            }
        }
        bestGamma = __shfl_sync(FULL, bestGamma, 0);
        bestI = __shfl_sync(FULL, bestI, 0);
        bestJ = __shfl_sync(FULL, bestJ, 0);
    }
    float sol = (i == bestI) ? bestGamma : ((i == bestJ) ? (1.0f - bestGamma) : 0.0f);
    solS[i] = sol;
    __syncwarp();

    // ---- main iteration (break == reference's done-freeze) ----
    for (int it = 0; it < MAX_ITER; ++it) {
        float Gsol = rowdot(&Gs[i][0], solS);
        float grad = -Gsol;

        // _next_point
        float mean = warpsum(grad) * (1.0f / 32.0f);
        float proj = grad - mean;
        float tm1 = (proj < 0.0f) ? (-sol / proj) : INFINITY;
        float tm2 = (proj > 0.0f) ? ((1.0f - sol) / proj) : INFINITY;
        float m1 = warpmin((tm1 > 1e-7f) ? tm1 : INFINITY);
        float tt = (m1 < INFINITY) ? m1 : 1.0f;
        float m2 = warpmin((tm2 > 1e-7f) ? tm2 : INFINITY);
        tt = fminf(tt, m2);
        float nxt = proj * tt + sol;

        // _proj_simplex: descending bitonic sort across the warp
        float s = nxt;
        #pragma unroll
        for (int k = 2; k <= 32; k <<= 1) {
            #pragma unroll
            for (int j = k >> 1; j > 0; j >>= 1) {
                float o = __shfl_xor_sync(FULL, s, j);
                bool lower = (i & j) == 0;
                bool asc   = (i & k) != 0;
                s = (lower == asc) ? fminf(s, o) : fmaxf(s, o);
            }
        }
        float cs = s;
        #pragma unroll
        for (int o = 1; o < 32; o <<= 1) {
            float v = __shfl_up_sync(FULL, cs, o);
            if (i >= o) cs += v;
        }
        float tmpmax = (cs - 1.0f) / (float)(i + 1);
        float snext = __shfl_down_sync(FULL, s, 1);
        bool cond = (i < 31) && (tmpmax > snext);
        unsigned bal = __ballot_sync(FULL, cond);
        int first = bal ? (__ffs(bal) - 1) : 31;
        float tmax = __shfl_sync(FULL, tmpmax, first);
        float newp = fmaxf(nxt - tmax, 0.0f);

        __syncwarp();
        newpS[i] = newp;
        __syncwarp();

        float Gn = rowdot(&Gs[i][0], newpS);

        float v11 = warpsum(sol * Gsol);
        float v12 = warpsum(sol * Gn);
        float v22 = warpsum(newp * Gn);
        float gamma, cost;
        line2(v11, v12, v22, &gamma, &cost);

        float ns = gamma * sol + (1.0f - gamma) * newp;
        float diff = warpsum(fabsf(ns - sol));
        if (diff < STOP_CRIT) break;   // reference freezes OLD sol from here on
        sol = ns;
        __syncwarp();
        solS[i] = sol;
        __syncwarp();
    }

    out[i] = sol;
}

// ---------------------------------------------------------------------------
extern "C" void kernel_launch(void* const* d_in, const int* in_sizes, int n_in,
                              void* d_out, int out_size) {
    const float* vecs = (const float*)d_in[0];
    float* out = (float*)d_out;
    (void)in_sizes; (void)n_in; (void)out_size;

    cudaFuncSetAttribute(gram_partial_kernel,
                         cudaFuncAttributeMaxDynamicSharedMemorySize, SMEM_BYTES);
    gram_partial_kernel<<<NBLK, TPB, SMEM_BYTES>>>(vecs);
    solver_kernel<<<1, 1024>>>(out);
}

// round 12
// speedup vs baseline: 2.3101x; 1.1591x over previous
#include <cuda_runtime.h>
#include <math.h>

#define N 32
#define D 2097152
#define D4 (D/4)
#define NBLK 148              // one block per SM, single wave
#define TPB 512
#define STR4 67               // smem row stride in float4 (conflict-free LDS pattern)
#define BUF_F4 (N * STR4)     // float4s per buffer (2144)
#define BUF_BYTES (BUF_F4 * 16)       // 34304
#define NBUF 3
#define SMEM_BYTES (NBUF * BUF_BYTES) // 102912
#define ROW_BYTES 1024        // 64 float4 per row per tile
#define TILE_BYTES (N * ROW_BYTES)    // 32768
#define NPAIR 10              // block pairs (I,J), I<=J, of 4x4 grid of 8x8 blocks
#define NACC  (NPAIR * 2)     // accs per thread (2 col-halves per pair)
#define MAX_ITER 250
#define STOP_CRIT 1e-6f
#define EPS_LS 1e-8f

__device__ float g_partial[NBLK * N * N];

// block-pair enumeration (I <= J)
__device__ __constant__ int c_PI[NPAIR] = {0,0,0,0,1,1,1,2,2,3};
__device__ __constant__ int c_PJ[NPAIR] = {0,1,2,3,1,2,3,2,3,3};

// ---------------------------------------------------------------------------
// PTX helpers
// ---------------------------------------------------------------------------
__device__ __forceinline__ void ffma2(unsigned long long& d,
                                      unsigned long long a,
                                      unsigned long long b) {
    asm("fma.rn.f32x2 %0, %1, %2, %0;" : "+l"(d) : "l"(a), "l"(b));
}
__device__ __forceinline__ float2 ull2f2(unsigned long long v) {
    float2 r;
    asm("mov.b64 {%0, %1}, %2;" : "=f"(r.x), "=f"(r.y) : "l"(v));
    return r;
}
__device__ __forceinline__ void mbar_init(unsigned mbar, unsigned count) {
    asm volatile("mbarrier.init.shared.b64 [%0], %1;" :: "r"(mbar), "r"(count) : "memory");
}
__device__ __forceinline__ void mbar_expect_tx(unsigned mbar, unsigned bytes) {
    asm volatile("mbarrier.arrive.expect_tx.shared.b64 _, [%0], %1;"
                 :: "r"(mbar), "r"(bytes) : "memory");
}
__device__ __forceinline__ void mbar_wait(unsigned mbar, unsigned parity) {
    asm volatile(
        "{\n\t"
        ".reg .pred P;\n\t"
        "W_%=:\n\t"
        "mbarrier.try_wait.parity.acquire.cta.shared::cta.b64 P, [%0], %1, 0x989680;\n\t"
        "@P bra D_%=;\n\t"
        "bra W_%=;\n\t"
        "D_%=:\n\t"
        "}" :: "r"(mbar), "r"(parity) : "memory");
}
__device__ __forceinline__ void bulk_cp(unsigned dst, const void* src,
                                        unsigned bytes, unsigned mbar) {
    asm volatile(
        "cp.async.bulk.shared::cluster.global.mbarrier::complete_tx::bytes "
        "[%0], [%1], %2, [%3];"
        :: "r"(dst), "l"(src), "r"(bytes), "r"(mbar) : "memory");
}

// ---------------------------------------------------------------------------
// Kernel 1: partial Gram, symmetric (block-upper-triangle only).
// 512 threads = 16 k-groups (one warp each) x 32 output-threads.
// Per thread: 20 f32x2 accs = entries (8I+ti, 8J+tj+4h) over the 10 (I<=J)
// block pairs. Triple-buffered cp.async.bulk pipeline, mirror write at end.
// ---------------------------------------------------------------------------
__global__ __launch_bounds__(TPB, 1)
void gram_partial_kernel(const float* __restrict__ vecs) {
    extern __shared__ float4 smem_dyn[];
    __shared__ unsigned long long barmem[NBUF];

    const int tid = threadIdx.x;
    const int blk = blockIdx.x;
    const int g  = tid >> 5;        // 0..15 : K-group (= warp id)
    const int t  = tid & 31;        // 0..31 : output-tile thread
    const int ti = t >> 2;          // 0..7  : row within block
    const int tj = t & 3;           // 0..3  : col base within block

    unsigned long long acc[NACC];   // acc[p*2+h]
    #pragma unroll
    for (int e = 0; e < NACC; ++e) acc[e] = 0ULL;

    const int numTiles = D / 256;   // 8192
    const int nT = (numTiles - blk + NBLK - 1) / NBLK;

    const unsigned sbase = (unsigned)__cvta_generic_to_shared(smem_dyn);
    unsigned bar[NBUF];
    #pragma unroll
    for (int b = 0; b < NBUF; ++b)
        bar[b] = (unsigned)__cvta_generic_to_shared(&barmem[b]);

    if (tid == 0) {
        #pragma unroll
        for (int b = 0; b < NBUF; ++b) mbar_init(bar[b], 1);
    }
    __syncthreads();

    const int lane = tid;           // warp 0 only: row id 0..31

    // warp-0 collective: issue tile m into buffer m%NBUF
    auto issue = [&](int m) {
        const int b = m % NBUF;
        const unsigned mbar = bar[b];
        if (lane == 0) mbar_expect_tx(mbar, TILE_BYTES);
        __syncwarp();
        const int tile = blk + m * NBLK;
        const float* src = vecs + (size_t)lane * D + (size_t)tile * 256;
        const unsigned dst = sbase + (unsigned)b * BUF_BYTES
                                   + (unsigned)lane * (STR4 * 16);
        bulk_cp(dst, src, ROW_BYTES, mbar);
    };

    if (tid < 32) {
        if (0 < nT) issue(0);
        if (1 < nT) issue(1);
        if (2 < nT) issue(2);
    }

    for (int m = 0; m < nT; ++m) {
        const int b = m % NBUF;
        mbar_wait(bar[b], (m / NBUF) & 1);

        const ulonglong2* __restrict__ sm8 =
            (const ulonglong2*)(smem_dyn + b * BUF_F4);

        #pragma unroll
        for (int kk = 0; kk < 4; ++kk) {
            const int k4 = (g << 2) + kk;
            // row operands: one per block-row I
            ulonglong2 av[4];
            #pragma unroll
            for (int I = 0; I < 4; ++I)
                av[I] = sm8[(I * 8 + ti) * STR4 + k4];
            // col operands: two per block-col J
            ulonglong2 bv[4][2];
            #pragma unroll
            for (int J = 0; J < 4; ++J) {
                bv[J][0] = sm8[(J * 8 + tj)     * STR4 + k4];
                bv[J][1] = sm8[(J * 8 + tj + 4) * STR4 + k4];
            }
            // 10 block pairs, I <= J
            int p = 0;
            #pragma unroll
            for (int I = 0; I < 4; ++I) {
                #pragma unroll
                for (int J = I; J < 4; ++J, ++p) {
                    #pragma unroll
                    for (int h = 0; h < 2; ++h) {
                        const int e = p * 2 + h;
                        ffma2(acc[e], av[I].x, bv[J][h].x);
                        ffma2(acc[e], av[I].y, bv[J][h].y);
                    }
                }
            }
        }

        __syncthreads();                 // all warps done reading buf b
        if (m + NBUF < nT && tid < 32) issue(m + NBUF);
    }

    // collapse packed pairs -> scalar accumulators
    float facc[NACC];
    #pragma unroll
    for (int e = 0; e < NACC; ++e) {
        float2 p = ull2f2(acc[e]);
        facc[e] = p.x + p.y;
    }

    __syncthreads();
    // deterministic cross-group reduction: 16 -> 8 -> 4 -> 2 -> 1 groups
    float* sbuf = (float*)smem_dyn;      // all async copies consumed by now
    for (int half = 8; half >= 1; half >>= 1) {
        __syncthreads();
        if (g >= half && g < 2 * half) {
            float* dst = sbuf + ((g - half) * 32 + t) * NACC;
            #pragma unroll
            for (int e = 0; e < NACC; ++e) dst[e] = facc[e];
        }
        __syncthreads();
        if (g < half) {
            const float* src = sbuf + (g * 32 + t) * NACC;
            #pragma unroll
            for (int e = 0; e < NACC; ++e) facc[e] += src[e];
        }
    }

    if (g == 0) {
        float* dst = g_partial + blk * (N * N);
        #pragma unroll
        for (int p = 0; p < NPAIR; ++p) {
            const int I = c_PI[p], J = c_PJ[p];
            #pragma unroll
            for (int h = 0; h < 2; ++h) {
                const int r = I * 8 + ti;
                const int c = J * 8 + tj + 4 * h;
                const float v = facc[p * 2 + h];
                dst[r * N + c] = v;
                if (I != J) dst[c * N + r] = v;   // mirror (identical value)
            }
        }
    }
}

// ---------------------------------------------------------------------------
// Kernel 2: fused partial-reduction + min-norm Frank-Wolfe solver.
// 1024 threads reduce the 148 partial Grams into smem; warp 0 then iterates.
// ---------------------------------------------------------------------------
__device__ __forceinline__ float warpsum(float v) {
    #pragma unroll
    for (int o = 16; o; o >>= 1) v += __shfl_xor_sync(0xffffffffu, v, o);
    return v;
}
__device__ __forceinline__ float warpmin(float v) {
    #pragma unroll
    for (int o = 16; o; o >>= 1) v = fminf(v, __shfl_xor_sync(0xffffffffu, v, o));
    return v;
}
__device__ __forceinline__ void line2(float v11, float v12, float v22,
                                      float* gamma, float* cost) {
    float gg = (v22 - v12) / (v11 + v22 - 2.0f * v12 + EPS_LS);
    float c  = v22 + gg * (v12 - v22);
    float gm = (v12 >= v22) ? 0.0f : gg;
    gm       = (v12 >= v11) ? 1.0f : gm;
    float cc = (v12 >= v22) ? v22 : c;
    cc       = (v12 >= v11) ? v11 : cc;
    *gamma = gm; *cost = cc;
}

// 4-way split matvec: depth-8 chains + 2 adds instead of 32 serial FMAs
__device__ __forceinline__ float rowdot(const float* __restrict__ Grow,
                                        const float* __restrict__ x) {
    float p0 = 0.f, p1 = 0.f, p2 = 0.f, p3 = 0.f;
    #pragma unroll
    for (int j = 0; j < 8; ++j) {
        p0 += Grow[j]      * x[j];
        p1 += Grow[j + 8]  * x[j + 8];
        p2 += Grow[j + 16] * x[j + 16];
        p3 += Grow[j + 24] * x[j + 24];
    }
    return (p0 + p1) + (p2 + p3);
}

__global__ void solver_kernel(float* __restrict__ out) {
    __shared__ float Gs[N][N + 1];
    __shared__ float solS[N], newpS[N];
    const unsigned FULL = 0xffffffffu;
    const int tid = threadIdx.x;

    // reduce 148 partials -> Gs (coalesced: thread e reads g_partial[b*1024+e])
    {
        float s = 0.0f;
        #pragma unroll 4
        for (int b = 0; b < NBLK; ++b) s += g_partial[b * (N * N) + tid];
        Gs[tid >> 5][tid & 31] = s;
    }
    __syncthreads();
    if (tid >= 32) return;

    const int i = tid;

    // ---- planar init: best pair by line-solver cost (first-min tiebreak) ----
    float bestCost = INFINITY, bestGamma = 0.0f;
    int bestLin = 1 << 30, bestI = 0, bestJ = 1;
    {
        float vii = Gs[i][i];
        int lin = i * 31 - (i * (i - 1)) / 2;    // triu row-major base index
        for (int j = i + 1; j < N; ++j, ++lin) {
            float gamma, cost;
            line2(vii, Gs[i][j], Gs[j][j], &gamma, &cost);
            if (cost < bestCost || (cost == bestCost && lin < bestLin)) {
                bestCost = cost; bestLin = lin; bestGamma = gamma;
                bestI = i; bestJ = j;
            }
        }
        #pragma unroll
        for (int o = 16; o; o >>= 1) {
            float oc = __shfl_down_sync(FULL, bestCost, o);
            int   ol = __shfl_down_sync(FULL, bestLin, o);
            float og = __shfl_down_sync(FULL, bestGamma, o);
            int   oi = __shfl_down_sync(FULL, bestI, o);
            int   oj = __shfl_down_sync(FULL, bestJ, o);
            if (oc < bestCost || (oc == bestCost && ol < bestLin)) {
                bestCost = oc; bestLin = ol; bestGamma = og; bestI = oi; bestJ = oj;
            }
        }
        bestGamma = __shfl_sync(FULL, bestGamma, 0);
        bestI = __shfl_sync(FULL, bestI, 0);
        bestJ = __shfl_sync(FULL, bestJ, 0);
    }
    float sol = (i == bestI) ? bestGamma : ((i == bestJ) ? (1.0f - bestGamma) : 0.0f);
    solS[i] = sol;
    __syncwarp();

    // ---- main iteration (break == reference's done-freeze) ----
    for (int it = 0; it < MAX_ITER; ++it) {
        float Gsol = rowdot(&Gs[i][0], solS);
        float grad = -Gsol;

        // _next_point
        float mean = warpsum(grad) * (1.0f / 32.0f);
        float proj = grad - mean;
        float tm1 = (proj < 0.0f) ? (-sol / proj) : INFINITY;
        float tm2 = (proj > 0.0f) ? ((1.0f - sol) / proj) : INFINITY;
        float m1 = warpmin((tm1 > 1e-7f) ? tm1 : INFINITY);
        float tt = (m1 < INFINITY) ? m1 : 1.0f;
        float m2 = warpmin((tm2 > 1e-7f) ? tm2 : INFINITY);
        tt = fminf(tt, m2);
        float nxt = proj * tt + sol;

        // _proj_simplex: descending bitonic sort across the warp
        float s = nxt;
        #pragma unroll
        for (int k = 2; k <= 32; k <<= 1) {
            #pragma unroll
            for (int j = k >> 1; j > 0; j >>= 1) {
                float o = __shfl_xor_sync(FULL, s, j);
                bool lower = (i & j) == 0;
                bool asc   = (i & k) != 0;
                s = (lower == asc) ? fminf(s, o) : fmaxf(s, o);
            }
        }
        float cs = s;
        #pragma unroll
        for (int o = 1; o < 32; o <<= 1) {
            float v = __shfl_up_sync(FULL, cs, o);
            if (i >= o) cs += v;
        }
        float tmpmax = (cs - 1.0f) / (float)(i + 1);
        float snext = __shfl_down_sync(FULL, s, 1);
        bool cond = (i < 31) && (tmpmax > snext);
        unsigned bal = __ballot_sync(FULL, cond);
        int first = bal ? (__ffs(bal) - 1) : 31;
        float tmax = __shfl_sync(FULL, tmpmax, first);
        float newp = fmaxf(nxt - tmax, 0.0f);

        __syncwarp();
        newpS[i] = newp;
        __syncwarp();

        float Gn = rowdot(&Gs[i][0], newpS);

        float v11 = warpsum(sol * Gsol);
        float v12 = warpsum(sol * Gn);
        float v22 = warpsum(newp * Gn);
        float gamma, cost;
        line2(v11, v12, v22, &gamma, &cost);

        float ns = gamma * sol + (1.0f - gamma) * newp;
        float diff = warpsum(fabsf(ns - sol));
        if (diff < STOP_CRIT) break;   // reference freezes OLD sol from here on
        sol = ns;
        __syncwarp();
        solS[i] = sol;
        __syncwarp();
    }

    out[i] = sol;
}

// ---------------------------------------------------------------------------
extern "C" void kernel_launch(void* const* d_in, const int* in_sizes, int n_in,
                              void* d_out, int out_size) {
    const float* vecs = (const float*)d_in[0];
    float* out = (float*)d_out;
    (void)in_sizes; (void)n_in; (void)out_size;

    cudaFuncSetAttribute(gram_partial_kernel,
                         cudaFuncAttributeMaxDynamicSharedMemorySize, SMEM_BYTES);
    gram_partial_kernel<<<NBLK, TPB, SMEM_BYTES>>>(vecs);
    solver_kernel<<<1, 1024>>>(out);
}

// round 14
// speedup vs baseline: 2.3726x; 1.0270x over previous
#include <cuda_runtime.h>
#include <math.h>

#define N 32
#define D 2097152
#define NBLK 148              // one block per SM, single wave
#define TPB 256               // 8 warps: 2x4 grid of 16x8 mma tiles
#define TILE_COLS 256         // k-cols per tile
#define NTILES (D / TILE_COLS)        // 8192
#define STRIDEF 260           // floats per smem row: bank = (4*row+tig)%32, conflict-free
#define ROW_BYTES 1024        // 256 floats copied per row
#define ROW_PITCH (STRIDEF * 4)       // 1040 bytes (16B aligned)
#define BUF_BYTES (N * ROW_PITCH)     // 33280
#define NBUF 4
#define SMEM_BYTES (NBUF * BUF_BYTES) // 133120
#define TX_BYTES (N * ROW_BYTES)      // 32768 actually transferred
#define MAX_ITER 250
#define STOP_CRIT 1e-6f
#define EPS_LS 1e-8f

__device__ float g_partial[NBLK * N * N];

// ---------------------------------------------------------------------------
// PTX helpers
// ---------------------------------------------------------------------------
__device__ __forceinline__ void mbar_init(unsigned mbar, unsigned count) {
    asm volatile("mbarrier.init.shared.b64 [%0], %1;" :: "r"(mbar), "r"(count) : "memory");
}
__device__ __forceinline__ void mbar_expect_tx(unsigned mbar, unsigned bytes) {
    asm volatile("mbarrier.arrive.expect_tx.shared.b64 _, [%0], %1;"
                 :: "r"(mbar), "r"(bytes) : "memory");
}
__device__ __forceinline__ void mbar_wait(unsigned mbar, unsigned parity) {
    asm volatile(
        "{\n\t"
        ".reg .pred P;\n\t"
        "W_%=:\n\t"
        "mbarrier.try_wait.parity.acquire.cta.shared::cta.b64 P, [%0], %1, 0x989680;\n\t"
        "@P bra D_%=;\n\t"
        "bra W_%=;\n\t"
        "D_%=:\n\t"
        "}" :: "r"(mbar), "r"(parity) : "memory");
}
__device__ __forceinline__ void bulk_cp(unsigned dst, const void* src,
                                        unsigned bytes, unsigned mbar) {
    asm volatile(
        "cp.async.bulk.shared::cluster.global.mbarrier::complete_tx::bytes "
        "[%0], [%1], %2, [%3];"
        :: "r"(dst), "l"(src), "r"(bytes), "r"(mbar) : "memory");
}
// m16n8k8 tf32 mma (sm_80+ baseline feature; compiles for plain sm_103)
__device__ __forceinline__ void mma_tf32(float& c0, float& c1, float& c2, float& c3,
                                         unsigned a0, unsigned a1, unsigned a2, unsigned a3,
                                         unsigned b0, unsigned b1) {
    asm("mma.sync.aligned.m16n8k8.row.col.f32.tf32.tf32.f32 "
        "{%0,%1,%2,%3}, {%4,%5,%6,%7}, {%8,%9}, {%0,%1,%2,%3};"
        : "+f"(c0), "+f"(c1), "+f"(c2), "+f"(c3)
        : "r"(a0), "r"(a1), "r"(a2), "r"(a3), "r"(b0), "r"(b1));
}

// ---------------------------------------------------------------------------
// Kernel 1: tf32 tensor-core partial Gram (legacy HMMA path).
// Per SM: 8 warps, warp w owns output tile (rows 16*(w/4)+, cols 8*(w%4)+).
// Each tile of 256 k-cols: 32 mma.sync.m16n8k8 per warp, fragments loaded
// straight from smem (conflict-free by stride-260 construction). Raw fp32
// bits feed the tf32 MMA (hardware truncation == uniform scale + tiny noise).
// Quadruple-buffered cp.async.bulk pipeline (warp 0 issues 32x 1KB rows).
// ---------------------------------------------------------------------------
__global__ __launch_bounds__(TPB, 1)
void gram_tc_kernel(const float* __restrict__ vecs) {
    extern __shared__ float smem_dyn[];
    __shared__ unsigned long long barmem[NBUF];

    const int tid  = threadIdx.x;
    const int blk  = blockIdx.x;
    const int wid  = tid >> 5;
    const int lane = tid & 31;
    const int gid  = lane >> 2;      // groupID   (0..7)
    const int tig  = lane & 3;       // thread-in-group (0..3)
    const int moff = (wid >> 2) * 16;    // 0 or 16
    const int noff = (wid & 3) * 8;      // 0,8,16,24

    float c0 = 0.f, c1 = 0.f, c2 = 0.f, c3 = 0.f;

    const int nT = (NTILES - blk + NBLK - 1) / NBLK;

    const unsigned sbase = (unsigned)__cvta_generic_to_shared(smem_dyn);
    unsigned bar[NBUF];
    #pragma unroll
    for (int b = 0; b < NBUF; ++b)
        bar[b] = (unsigned)__cvta_generic_to_shared(&barmem[b]);

    if (tid == 0) {
        #pragma unroll
        for (int b = 0; b < NBUF; ++b) mbar_init(bar[b], 1);
    }
    __syncthreads();

    // warp-0 collective: issue tile m into buffer m%NBUF (one 1KB row per lane)
    auto issue = [&](int m) {
        const int b = m % NBUF;
        if (lane == 0) mbar_expect_tx(bar[b], TX_BYTES);
        __syncwarp();
        const int tile = blk + m * NBLK;
        const float* src = vecs + (size_t)lane * D + (size_t)tile * TILE_COLS;
        const unsigned dst = sbase + (unsigned)b * BUF_BYTES
                                   + (unsigned)lane * ROW_PITCH;
        bulk_cp(dst, src, ROW_BYTES, bar[b]);
    };

    if (tid < 32) {
        #pragma unroll
        for (int m = 0; m < NBUF; ++m) if (m < nT) issue(m);
    }

    // pointers to this thread's fragment rows (offsets within a buffer)
    const int offA0 = (moff + gid)     * STRIDEF + tig;
    const int offA8 = (moff + gid + 8) * STRIDEF + tig;
    const int offB  = (noff + gid)     * STRIDEF + tig;

    for (int m = 0; m < nT; ++m) {
        const int b = m % NBUF;
        mbar_wait(bar[b], (unsigned)((m / NBUF) & 1));

        const float* sm = smem_dyn + (size_t)b * (BUF_BYTES / 4);
        const float* pa0 = sm + offA0;
        const float* pa8 = sm + offA8;
        const float* pb  = sm + offB;

        #pragma unroll 8
        for (int kc = 0; kc < TILE_COLS / 8; ++kc) {
            const int k0 = kc * 8;
            unsigned a0 = __float_as_uint(pa0[k0]);
            unsigned a1 = __float_as_uint(pa8[k0]);
            unsigned a2 = __float_as_uint(pa0[k0 + 4]);
            unsigned a3 = __float_as_uint(pa8[k0 + 4]);
            unsigned b0 = __float_as_uint(pb [k0]);
            unsigned b1 = __float_as_uint(pb [k0 + 4]);
            mma_tf32(c0, c1, c2, c3, a0, a1, a2, a3, b0, b1);
        }

        __syncthreads();                 // all warps done reading buf b
        if (m + NBUF < nT && tid < 32) issue(m + NBUF);
    }

    // epilogue: each warp writes its 16x8 C tile (no cross-warp reduction)
    {
        float* dst = g_partial + blk * (N * N);
        const int r0 = moff + gid;
        const int r1 = moff + gid + 8;
        const int cb = noff + 2 * tig;
        dst[r0 * N + cb]     = c0;
        dst[r0 * N + cb + 1] = c1;
        dst[r1 * N + cb]     = c2;
        dst[r1 * N + cb + 1] = c3;
    }
}

// ---------------------------------------------------------------------------
// Kernel 2: fused partial-reduction + min-norm Frank-Wolfe solver (unchanged).
// ---------------------------------------------------------------------------
__device__ __forceinline__ float warpsum(float v) {
    #pragma unroll
    for (int o = 16; o; o >>= 1) v += __shfl_xor_sync(0xffffffffu, v, o);
    return v;
}
__device__ __forceinline__ float warpmin(float v) {
    #pragma unroll
    for (int o = 16; o; o >>= 1) v = fminf(v, __shfl_xor_sync(0xffffffffu, v, o));
    return v;
}
__device__ __forceinline__ void line2(float v11, float v12, float v22,
                                      float* gamma, float* cost) {
    float gg = (v22 - v12) / (v11 + v22 - 2.0f * v12 + EPS_LS);
    float c  = v22 + gg * (v12 - v22);
    float gm = (v12 >= v22) ? 0.0f : gg;
    gm       = (v12 >= v11) ? 1.0f : gm;
    float cc = (v12 >= v22) ? v22 : c;
    cc       = (v12 >= v11) ? v11 : cc;
    *gamma = gm; *cost = cc;
}
__device__ __forceinline__ float rowdot(const float* __restrict__ Grow,
                                        const float* __restrict__ x) {
    float p0 = 0.f, p1 = 0.f, p2 = 0.f, p3 = 0.f;
    #pragma unroll
    for (int j = 0; j < 8; ++j) {
        p0 += Grow[j]      * x[j];
        p1 += Grow[j + 8]  * x[j + 8];
        p2 += Grow[j + 16] * x[j + 16];
        p3 += Grow[j + 24] * x[j + 24];
    }
    return (p0 + p1) + (p2 + p3);
}

__global__ void solver_kernel(float* __restrict__ out) {
    __shared__ float Gs[N][N + 1];
    __shared__ float solS[N], newpS[N];
    const unsigned FULL = 0xffffffffu;
    const int tid = threadIdx.x;

    {
        float s = 0.0f;
        #pragma unroll 4
        for (int b = 0; b < NBLK; ++b) s += g_partial[b * (N * N) + tid];
        Gs[tid >> 5][tid & 31] = s;
    }
    __syncthreads();
    if (tid >= 32) return;

    const int i = tid;

    float bestCost = INFINITY, bestGamma = 0.0f;
    int bestLin = 1 << 30, bestI = 0, bestJ = 1;
    {
        float vii = Gs[i][i];
        int lin = i * 31 - (i * (i - 1)) / 2;
        for (int j = i + 1; j < N; ++j, ++lin) {
            float gamma, cost;
            line2(vii, Gs[i][j], Gs[j][j], &gamma, &cost);
            if (cost < bestCost || (cost == bestCost && lin < bestLin)) {
                bestCost = cost; bestLin = lin; bestGamma = gamma;
                bestI = i; bestJ = j;
            }
        }
        #pragma unroll
        for (int o = 16; o; o >>= 1) {
            float oc = __shfl_down_sync(FULL, bestCost, o);
            int   ol = __shfl_down_sync(FULL, bestLin, o);
            float og = __shfl_down_sync(FULL, bestGamma, o);
            int   oi = __shfl_down_sync(FULL, bestI, o);
            int   oj = __shfl_down_sync(FULL, bestJ, o);
            if (oc < bestCost || (oc == bestCost && ol < bestLin)) {
                bestCost = oc; bestLin = ol; bestGamma = og; bestI = oi; bestJ = oj;
            }
        }
        bestGamma = __shfl_sync(FULL, bestGamma, 0);
        bestI = __shfl_sync(FULL, bestI, 0);
        bestJ = __shfl_sync(FULL, bestJ, 0);
    }
    float sol = (i == bestI) ? bestGamma : ((i == bestJ) ? (1.0f - bestGamma) : 0.0f);
    solS[i] = sol;
    __syncwarp();

    for (int it = 0; it < MAX_ITER; ++it) {
        float Gsol = rowdot(&Gs[i][0], solS);
        float grad = -Gsol;

        float mean = warpsum(grad) * (1.0f / 32.0f);
        float proj = grad - mean;
        float tm1 = (proj < 0.0f) ? (-sol / proj) : INFINITY;
        float tm2 = (proj > 0.0f) ? ((1.0f - sol) / proj) : INFINITY;
        float m1 = warpmin((tm1 > 1e-7f) ? tm1 : INFINITY);
        float tt = (m1 < INFINITY) ? m1 : 1.0f;
        float m2 = warpmin((tm2 > 1e-7f) ? tm2 : INFINITY);
        tt = fminf(tt, m2);
        float nxt = proj * tt + sol;

        float s = nxt;
        #pragma unroll
        for (int k = 2; k <= 32; k <<= 1) {
            #pragma unroll
            for (int j = k >> 1; j > 0; j >>= 1) {
                float o = __shfl_xor_sync(FULL, s, j);
                bool lower = (i & j) == 0;
                bool asc   = (i & k) != 0;
                s = (lower == asc) ? fminf(s, o) : fmaxf(s, o);
            }
        }
        float cs = s;
        #pragma unroll
        for (int o = 1; o < 32; o <<= 1) {
            float v = __shfl_up_sync(FULL, cs, o);
            if (i >= o) cs += v;
        }
        float tmpmax = (cs - 1.0f) / (float)(i + 1);
        float snext = __shfl_down_sync(FULL, s, 1);
        bool cond = (i < 31) && (tmpmax > snext);
        unsigned bal = __ballot_sync(FULL, cond);
        int first = bal ? (__ffs(bal) - 1) : 31;
        float tmax = __shfl_sync(FULL, tmpmax, first);
        float newp = fmaxf(nxt - tmax, 0.0f);

        __syncwarp();
        newpS[i] = newp;
        __syncwarp();

        float Gn = rowdot(&Gs[i][0], newpS);

        float v11 = warpsum(sol * Gsol);
        float v12 = warpsum(sol * Gn);
        float v22 = warpsum(newp * Gn);
        float gamma, cost;
        line2(v11, v12, v22, &gamma, &cost);

        float ns = gamma * sol + (1.0f - gamma) * newp;
        float diff = warpsum(fabsf(ns - sol));
        if (diff < STOP_CRIT) break;
        sol = ns;
        __syncwarp();
        solS[i] = sol;
        __syncwarp();
    }

    out[i] = sol;
}

// ---------------------------------------------------------------------------
extern "C" void kernel_launch(void* const* d_in, const int* in_sizes, int n_in,
                              void* d_out, int out_size) {
    const float* vecs = (const float*)d_in[0];
    float* out = (float*)d_out;
    (void)in_sizes; (void)n_in; (void)out_size;

    cudaFuncSetAttribute(gram_tc_kernel,
                         cudaFuncAttributeMaxDynamicSharedMemorySize, SMEM_BYTES);
    gram_tc_kernel<<<NBLK, TPB, SMEM_BYTES>>>(vecs);
    solver_kernel<<<1, 1024>>>(out);
}

// round 17
// speedup vs baseline: 2.8092x; 1.1840x over previous
#include <cuda_runtime.h>
#include <math.h>

#define N 32
#define D 2097152
#define NBLK 148              // one block per SM, single wave
#define TPB 256               // 8 warps: 2 row-blocks x 4 k-quarters
#define TILE_COLS 256         // k-cols per tile
#define NTILES (D / TILE_COLS)        // 8192
#define STRIDEF 260           // floats per smem row: bank = (4*row+tig)%32, conflict-free
#define ROW_BYTES 1024        // 256 floats copied per row
#define ROW_PITCH (STRIDEF * 4)       // 1040 bytes (16B aligned)
#define BUF_BYTES (N * ROW_PITCH)     // 33280
#define NBUF 4
#define SMEM_BYTES (NBUF * BUF_BYTES) // 133120
#define TX_BYTES (N * ROW_BYTES)      // 32768 actually transferred
#define MAX_ITER 250
#define STOP_CRIT 1e-6f
#define EPS_LS 1e-8f

__device__ float g_partial[NBLK * N * N];

// ---------------------------------------------------------------------------
// PTX helpers
// ---------------------------------------------------------------------------
__device__ __forceinline__ void mbar_init(unsigned mbar, unsigned count) {
    asm volatile("mbarrier.init.shared.b64 [%0], %1;" :: "r"(mbar), "r"(count) : "memory");
}
__device__ __forceinline__ void mbar_expect_tx(unsigned mbar, unsigned bytes) {
    asm volatile("mbarrier.arrive.expect_tx.shared.b64 _, [%0], %1;"
                 :: "r"(mbar), "r"(bytes) : "memory");
}
__device__ __forceinline__ void mbar_wait(unsigned mbar, unsigned parity) {
    asm volatile(
        "{\n\t"
        ".reg .pred P;\n\t"
        "W_%=:\n\t"
        "mbarrier.try_wait.parity.acquire.cta.shared::cta.b64 P, [%0], %1, 0x989680;\n\t"
        "@P bra D_%=;\n\t"
        "bra W_%=;\n\t"
        "D_%=:\n\t"
        "}" :: "r"(mbar), "r"(parity) : "memory");
}
__device__ __forceinline__ void bulk_cp(unsigned dst, const void* src,
                                        unsigned bytes, unsigned mbar) {
    asm volatile(
        "cp.async.bulk.shared::cluster.global.mbarrier::complete_tx::bytes "
        "[%0], [%1], %2, [%3];"
        :: "r"(dst), "l"(src), "r"(bytes), "r"(mbar) : "memory");
}
// m16n8k8 tf32 mma (sm_80+ baseline feature; compiles for plain sm_103)
__device__ __forceinline__ void mma_tf32(float* c,
                                         unsigned a0, unsigned a1, unsigned a2, unsigned a3,
                                         unsigned b0, unsigned b1) {
    asm("mma.sync.aligned.m16n8k8.row.col.f32.tf32.tf32.f32 "
        "{%0,%1,%2,%3}, {%4,%5,%6,%7}, {%8,%9}, {%0,%1,%2,%3};"
        : "+f"(c[0]), "+f"(c[1]), "+f"(c[2]), "+f"(c[3])
        : "r"(a0), "r"(a1), "r"(a2), "r"(a3), "r"(b0), "r"(b1));
}

// ---------------------------------------------------------------------------
// Kernel 1: tf32 tensor-core partial Gram.
// 8 warps = 2 row-blocks (m) x 4 k-quarters (q). Warp (m,q) computes the
// 16x32 output strip rows [16m,16m+16) over its 64-col k-quarter as 4
// INDEPENDENT 16x8 mma tiles (breaks the serial HMMA accumulator chain and
// amortizes A-fragment loads: 3 LDS per MMA instead of 6). End: 4-way
// cross-quarter reduction through smem. Quadruple-buffered cp.async.bulk
// pipeline (warp 0 issues 32x 1KB rows per tile).
// ---------------------------------------------------------------------------
__global__ __launch_bounds__(TPB, 1)
void gram_tc_kernel(const float* __restrict__ vecs) {
    extern __shared__ float smem_dyn[];
    __shared__ unsigned long long barmem[NBUF];

    const int tid  = threadIdx.x;
    const int blk  = blockIdx.x;
    const int wid  = tid >> 5;
    const int lane = tid & 31;
    const int gid  = lane >> 2;      // groupID (0..7)
    const int tig  = lane & 3;       // thread-in-group (0..3)
    const int mb   = wid >> 2;       // row block: 0 or 1
    const int q    = wid & 3;        // k-quarter: 0..3

    float c[4][4];
    #pragma unroll
    for (int n = 0; n < 4; ++n)
        #pragma unroll
        for (int e = 0; e < 4; ++e) c[n][e] = 0.0f;

    const int nT = (NTILES - blk + NBLK - 1) / NBLK;

    const unsigned sbase = (unsigned)__cvta_generic_to_shared(smem_dyn);
    unsigned bar[NBUF];
    #pragma unroll
    for (int b = 0; b < NBUF; ++b)
        bar[b] = (unsigned)__cvta_generic_to_shared(&barmem[b]);

    if (tid == 0) {
        #pragma unroll
        for (int b = 0; b < NBUF; ++b) mbar_init(bar[b], 1);
    }
    __syncthreads();

    // warp-0 collective: issue tile m into buffer m%NBUF (one 1KB row per lane)
    auto issue = [&](int m) {
        const int b = m % NBUF;
        if (lane == 0) mbar_expect_tx(bar[b], TX_BYTES);
        __syncwarp();
        const int tile = blk + m * NBLK;
        const float* src = vecs + (size_t)lane * D + (size_t)tile * TILE_COLS;
        const unsigned dst = sbase + (unsigned)b * BUF_BYTES
                                   + (unsigned)lane * ROW_PITCH;
        bulk_cp(dst, src, ROW_BYTES, bar[b]);
    };

    if (tid < 32) {
        #pragma unroll
        for (int m = 0; m < NBUF; ++m) if (m < nT) issue(m);
    }

    // fragment-row offsets within a buffer (k-quarter base folded in)
    const int kbase = q * 64;
    const int offA0 = (mb * 16 + gid)     * STRIDEF + tig + kbase;
    const int offA8 = (mb * 16 + gid + 8) * STRIDEF + tig + kbase;
    int offB[4];
    #pragma unroll
    for (int n = 0; n < 4; ++n)
        offB[n] = (n * 8 + gid) * STRIDEF + tig + kbase;

    for (int m = 0; m < nT; ++m) {
        const int b = m % NBUF;
        mbar_wait(bar[b], (unsigned)((m / NBUF) & 1));

        const float* sm = smem_dyn + (size_t)b * (BUF_BYTES / 4);
        const float* pa0 = sm + offA0;
        const float* pa8 = sm + offA8;

        #pragma unroll
        for (int kc = 0; kc < 8; ++kc) {
            const int k0 = kc * 8;
            unsigned a0 = __float_as_uint(pa0[k0]);
            unsigned a1 = __float_as_uint(pa8[k0]);
            unsigned a2 = __float_as_uint(pa0[k0 + 4]);
            unsigned a3 = __float_as_uint(pa8[k0 + 4]);
            #pragma unroll
            for (int n = 0; n < 4; ++n) {
                unsigned b0 = __float_as_uint(sm[offB[n] + k0]);
                unsigned b1 = __float_as_uint(sm[offB[n] + k0 + 4]);
                mma_tf32(c[n], a0, a1, a2, a3, b0, b1);
            }
        }

        __syncthreads();                 // all warps done reading buf b
        if (m + NBUF < nT && tid < 32) issue(m + NBUF);
    }

    // ---- cross-quarter reduction: red[q][32][32] in smem (16 KB) ----
    float* red = smem_dyn;               // all async copies consumed by now
    {
        const int r0 = mb * 16 + gid;
        const int r1 = mb * 16 + gid + 8;
        #pragma unroll
        for (int n = 0; n < 4; ++n) {
            const int cb = n * 8 + 2 * tig;
            red[q * 1024 + r0 * N + cb]     = c[n][0];
            red[q * 1024 + r0 * N + cb + 1] = c[n][1];
            red[q * 1024 + r1 * N + cb]     = c[n][2];
            red[q * 1024 + r1 * N + cb + 1] = c[n][3];
        }
    }
    __syncthreads();

    for (int e = tid; e < N * N; e += TPB) {
        float s = (red[e] + red[1024 + e]) + (red[2048 + e] + red[3072 + e]);
        g_partial[blk * (N * N) + e] = s;
    }
}

// ---------------------------------------------------------------------------
// Kernel 2: fused partial-reduction + min-norm Frank-Wolfe solver (unchanged).
// ---------------------------------------------------------------------------
__device__ __forceinline__ float warpsum(float v) {
    #pragma unroll
    for (int o = 16; o; o >>= 1) v += __shfl_xor_sync(0xffffffffu, v, o);
    return v;
}
__device__ __forceinline__ float warpmin(float v) {
    #pragma unroll
    for (int o = 16; o; o >>= 1) v = fminf(v, __shfl_xor_sync(0xffffffffu, v, o));
    return v;
}
__device__ __forceinline__ void line2(float v11, float v12, float v22,
                                      float* gamma, float* cost) {
    float gg = (v22 - v12) / (v11 + v22 - 2.0f * v12 + EPS_LS);
    float c  = v22 + gg * (v12 - v22);
    float gm = (v12 >= v22) ? 0.0f : gg;
    gm       = (v12 >= v11) ? 1.0f : gm;
    float cc = (v12 >= v22) ? v22 : c;
    cc       = (v12 >= v11) ? v11 : cc;
    *gamma = gm; *cost = cc;
}
__device__ __forceinline__ float rowdot(const float* __restrict__ Grow,
                                        const float* __restrict__ x) {
    float p0 = 0.f, p1 = 0.f, p2 = 0.f, p3 = 0.f;
    #pragma unroll
    for (int j = 0; j < 8; ++j) {
        p0 += Grow[j]      * x[j];
        p1 += Grow[j + 8]  * x[j + 8];
        p2 += Grow[j + 16] * x[j + 16];
        p3 += Grow[j + 24] * x[j + 24];
    }
    return (p0 + p1) + (p2 + p3);
}

__global__ void solver_kernel(float* __restrict__ out) {
    __shared__ float Gs[N][N + 1];
    __shared__ float solS[N], newpS[N];
    const unsigned FULL = 0xffffffffu;
    const int tid = threadIdx.x;

    {
        float s = 0.0f;
        #pragma unroll 4
        for (int b = 0; b < NBLK; ++b) s += g_partial[b * (N * N) + tid];
        Gs[tid >> 5][tid & 31] = s;
    }
    __syncthreads();
    if (tid >= 32) return;

    const int i = tid;

    float bestCost = INFINITY, bestGamma = 0.0f;
    int bestLin = 1 << 30, bestI = 0, bestJ = 1;
    {
        float vii = Gs[i][i];
        int lin = i * 31 - (i * (i - 1)) / 2;
        for (int j = i + 1; j < N; ++j, ++lin) {
            float gamma, cost;
            line2(vii, Gs[i][j], Gs[j][j], &gamma, &cost);
            if (cost < bestCost || (cost == bestCost && lin < bestLin)) {
                bestCost = cost; bestLin = lin; bestGamma = gamma;
                bestI = i; bestJ = j;
            }
        }
        #pragma unroll
        for (int o = 16; o; o >>= 1) {
            float oc = __shfl_down_sync(FULL, bestCost, o);
            int   ol = __shfl_down_sync(FULL, bestLin, o);
            float og = __shfl_down_sync(FULL, bestGamma, o);
            int   oi = __shfl_down_sync(FULL, bestI, o);
            int   oj = __shfl_down_sync(FULL, bestJ, o);
            if (oc < bestCost || (oc == bestCost && ol < bestLin)) {
                bestCost = oc; bestLin = ol; bestGamma = og; bestI = oi; bestJ = oj;
            }
        }
        bestGamma = __shfl_sync(FULL, bestGamma, 0);
        bestI = __shfl_sync(FULL, bestI, 0);
        bestJ = __shfl_sync(FULL, bestJ, 0);
    }
    float sol = (i == bestI) ? bestGamma : ((i == bestJ) ? (1.0f - bestGamma) : 0.0f);
    solS[i] = sol;
    __syncwarp();

    for (int it = 0; it < MAX_ITER; ++it) {
        float Gsol = rowdot(&Gs[i][0], solS);
        float grad = -Gsol;

        float mean = warpsum(grad) * (1.0f / 32.0f);
        float proj = grad - mean;
        float tm1 = (proj < 0.0f) ? (-sol / proj) : INFINITY;
        float tm2 = (proj > 0.0f) ? ((1.0f - sol) / proj) : INFINITY;
        float m1 = warpmin((tm1 > 1e-7f) ? tm1 : INFINITY);
        float tt = (m1 < INFINITY) ? m1 : 1.0f;
        float m2 = warpmin((tm2 > 1e-7f) ? tm2 : INFINITY);
        tt = fminf(tt, m2);
        float nxt = proj * tt + sol;

        float s = nxt;
        #pragma unroll
        for (int k = 2; k <= 32; k <<= 1) {
            #pragma unroll
            for (int j = k >> 1; j > 0; j >>= 1) {
                float o = __shfl_xor_sync(FULL, s, j);
                bool lower = (i & j) == 0;
                bool asc   = (i & k) != 0;
                s = (lower == asc) ? fminf(s, o) : fmaxf(s, o);
            }
        }
        float cs = s;
        #pragma unroll
        for (int o = 1; o < 32; o <<= 1) {
            float v = __shfl_up_sync(FULL, cs, o);
            if (i >= o) cs += v;
        }
        float tmpmax = (cs - 1.0f) / (float)(i + 1);
        float snext = __shfl_down_sync(FULL, s, 1);
        bool cond = (i < 31) && (tmpmax > snext);
        unsigned bal = __ballot_sync(FULL, cond);
        int first = bal ? (__ffs(bal) - 1) : 31;
        float tmax = __shfl_sync(FULL, tmpmax, first);
        float newp = fmaxf(nxt - tmax, 0.0f);

        __syncwarp();
        newpS[i] = newp;
        __syncwarp();

        float Gn = rowdot(&Gs[i][0], newpS);

        float v11 = warpsum(sol * Gsol);
        float v12 = warpsum(sol * Gn);
        float v22 = warpsum(newp * Gn);
        float gamma, cost;
        line2(v11, v12, v22, &gamma, &cost);

        float ns = gamma * sol + (1.0f - gamma) * newp;
        float diff = warpsum(fabsf(ns - sol));
        if (diff < STOP_CRIT) break;
        sol = ns;
        __syncwarp();
        solS[i] = sol;
        __syncwarp();
    }

    out[i] = sol;
}

// ---------------------------------------------------------------------------
extern "C" void kernel_launch(void* const* d_in, const int* in_sizes, int n_in,
                              void* d_out, int out_size) {
    const float* vecs = (const float*)d_in[0];
    float* out = (float*)d_out;
    (void)in_sizes; (void)n_in; (void)out_size;

    cudaFuncSetAttribute(gram_tc_kernel,
                         cudaFuncAttributeMaxDynamicSharedMemorySize, SMEM_BYTES);
    gram_tc_kernel<<<NBLK, TPB, SMEM_BYTES>>>(vecs);
    solver_kernel<<<1, 1024>>>(out);
}